// round 2
// baseline (speedup 1.0000x reference)
#include <cuda_runtime.h>
#include <cstdint>

// Problem constants
#define M_TOTAL 8192   // 4 * 2048
#define N_TOTAL 4096   // OUT_FEATURES
#define K_TOTAL 4096   // IN_FEATURES
#define NKT (K_TOTAL / BK)

// GEMM tiling
#define BM 128
#define BN 128
#define BK 32
#define LDA (BK + 4)   // padded smem stride (floats): (4*row + col) % 32 unique -> conflict-free

__constant__ float c_codebook[16] = {
    0.0f, 0.0052f, 0.6667f, 1.0f, 0.3333f, 0.5f, 0.1667f, 0.25f,
    0.0f, -0.0052f, -0.6667f, -1.0f, -0.3333f, -0.5f, -0.1667f, -0.25f};

// Scratch (device globals: allocation-free per harness rules)
__device__ __align__(16) float g_W[(size_t)N_TOTAL * K_TOTAL];  // dequantized, tf32-rounded, [N][K]
__device__ __align__(16) float g_X[(size_t)M_TOTAL * K_TOTAL];  // tf32-rounded activations, [M][K]

__device__ __forceinline__ float tf32_rna(float x) {
    uint32_t o;
    asm("cvt.rna.tf32.f32 %0, %1;" : "=r"(o) : "f"(x));
    return __uint_as_float(o);
}

__device__ __forceinline__ void cp_async16(void* smem_dst, const void* gsrc) {
    uint32_t d = (uint32_t)__cvta_generic_to_shared(smem_dst);
    asm volatile("cp.async.cg.shared.global [%0], [%1], 16;\n" ::"r"(d), "l"(gsrc));
}
__device__ __forceinline__ void cp_commit() {
    asm volatile("cp.async.commit_group;\n" ::: "memory");
}
template <int N>
__device__ __forceinline__ void cp_wait() {
    asm volatile("cp.async.wait_group %0;\n" ::"n"(N) : "memory");
}

// ---------------------------------------------------------------------------
// Kernel 1: dequant packed FP4 -> g_W (tf32-rounded fp32, [N][K] = K-major)
// Each int32 holds one byte: high nibble = element 2i, low nibble = 2i+1.
// Both elements of a pair share the same 64-wide scale block (2i is even).
// ---------------------------------------------------------------------------
__global__ void dequant_kernel(const int* __restrict__ wp, const float* __restrict__ scale) {
    int i = blockIdx.x * blockDim.x + threadIdx.x;
    if (i >= (N_TOTAL * K_TOTAL) / 2) return;
    int p = wp[i];
    int e0 = 2 * i;
    float s = scale[e0 >> 6];
    float w0 = c_codebook[(p >> 4) & 15] * s;
    float w1 = c_codebook[p & 15] * s;
    float2 v = make_float2(tf32_rna(w0), tf32_rna(w1));
    *reinterpret_cast<float2*>(&g_W[e0]) = v;
}

// ---------------------------------------------------------------------------
// Kernel 2: round x to tf32 (round-to-nearest, unbiased) -> g_X
// ---------------------------------------------------------------------------
__global__ void xround_kernel(const float* __restrict__ x) {
    size_t i = ((size_t)blockIdx.x * blockDim.x + threadIdx.x) * 4;
    float4 v = *reinterpret_cast<const float4*>(&x[i]);
    v.x = tf32_rna(v.x);
    v.y = tf32_rna(v.y);
    v.z = tf32_rna(v.z);
    v.w = tf32_rna(v.w);
    *reinterpret_cast<float4*>(&g_X[i]) = v;
}

// ---------------------------------------------------------------------------
// Kernel 3: GEMM  out[M][N] = g_X[M][K] * g_W[N][K]^T + bias
// 128x128x32 CTA tile, double-buffered cp.async, 8 warps (2x4), each warp
// 64x32 via m16n8k8 tf32 mma.sync (4 m-tiles x 4 n-tiles).
// ---------------------------------------------------------------------------
__global__ __launch_bounds__(256) void gemm_kernel(const float* __restrict__ bias,
                                                   float* __restrict__ out) {
    __shared__ __align__(16) float As[2][BM][LDA];
    __shared__ __align__(16) float Bs[2][BN][LDA];

    const int bm = blockIdx.y * BM;
    const int bn = blockIdx.x * BN;
    const int tid = threadIdx.x;
    const int wid = tid >> 5;
    const int lane = tid & 31;
    const int warp_m = (wid >> 2) * 64;  // 0 or 64
    const int warp_n = (wid & 3) * 32;   // 0,32,64,96

    const int ld_row = tid >> 3;        // 0..31 (per j step covers 32 rows)
    const int ld_seg = (tid & 7) * 4;   // float offset of 16B segment

    // --- tile loader (row stride 144 B: 16B-aligned segments) ---
    auto load_tiles = [&](int buf, int kt) {
        const int kbase = kt * BK;
#pragma unroll
        for (int j = 0; j < 4; j++) {
            int row = ld_row + j * 32;
            cp_async16(&As[buf][row][ld_seg],
                       &g_X[(size_t)(bm + row) * K_TOTAL + kbase + ld_seg]);
        }
#pragma unroll
        for (int j = 0; j < 4; j++) {
            int row = ld_row + j * 32;
            cp_async16(&Bs[buf][row][ld_seg],
                       &g_W[(size_t)(bn + row) * K_TOTAL + kbase + ld_seg]);
        }
    };

    float acc[4][4][4];
#pragma unroll
    for (int i = 0; i < 4; i++)
#pragma unroll
        for (int j = 0; j < 4; j++)
#pragma unroll
            for (int r = 0; r < 4; r++) acc[i][j][r] = 0.0f;

    load_tiles(0, 0);
    cp_commit();

    const int gr = lane >> 2;  // groupID
    const int gc = lane & 3;   // threadID in group

    for (int kt = 0; kt < NKT; kt++) {
        const int cur = kt & 1;
        if (kt + 1 < NKT) {
            load_tiles(cur ^ 1, kt + 1);
            cp_commit();
            cp_wait<1>();
        } else {
            cp_wait<0>();
        }
        __syncthreads();

#pragma unroll
        for (int ks = 0; ks < 4; ks++) {
            const int k0 = ks * 8;
            uint32_t a[4][4], b[4][2];
#pragma unroll
            for (int tm = 0; tm < 4; tm++) {
                const int m = warp_m + tm * 16;
                a[tm][0] = __float_as_uint(As[cur][m + gr][k0 + gc]);
                a[tm][1] = __float_as_uint(As[cur][m + gr + 8][k0 + gc]);
                a[tm][2] = __float_as_uint(As[cur][m + gr][k0 + gc + 4]);
                a[tm][3] = __float_as_uint(As[cur][m + gr + 8][k0 + gc + 4]);
            }
#pragma unroll
            for (int tn = 0; tn < 4; tn++) {
                const int n = warp_n + tn * 8;
                b[tn][0] = __float_as_uint(Bs[cur][n + gr][k0 + gc]);
                b[tn][1] = __float_as_uint(Bs[cur][n + gr][k0 + gc + 4]);
            }
#pragma unroll
            for (int tm = 0; tm < 4; tm++)
#pragma unroll
                for (int tn = 0; tn < 4; tn++) {
                    asm volatile(
                        "mma.sync.aligned.m16n8k8.row.col.f32.tf32.tf32.f32 "
                        "{%0,%1,%2,%3}, {%4,%5,%6,%7}, {%8,%9}, {%0,%1,%2,%3};"
                        : "+f"(acc[tm][tn][0]), "+f"(acc[tm][tn][1]),
                          "+f"(acc[tm][tn][2]), "+f"(acc[tm][tn][3])
                        : "r"(a[tm][0]), "r"(a[tm][1]), "r"(a[tm][2]), "r"(a[tm][3]),
                          "r"(b[tn][0]), "r"(b[tn][1]));
                }
        }
        __syncthreads();
    }

    // Epilogue: add bias, store (float2 per c-pair)
#pragma unroll
    for (int tm = 0; tm < 4; tm++) {
        const int m = bm + warp_m + tm * 16 + gr;
#pragma unroll
        for (int tn = 0; tn < 4; tn++) {
            const int n = bn + warp_n + tn * 8 + gc * 2;
            const float b0 = __ldg(&bias[n]);
            const float b1 = __ldg(&bias[n + 1]);
            float2 v0 = make_float2(acc[tm][tn][0] + b0, acc[tm][tn][1] + b1);
            float2 v1 = make_float2(acc[tm][tn][2] + b0, acc[tm][tn][3] + b1);
            *reinterpret_cast<float2*>(&out[(size_t)m * N_TOTAL + n]) = v0;
            *reinterpret_cast<float2*>(&out[(size_t)(m + 8) * N_TOTAL + n]) = v1;
        }
    }
}

extern "C" void kernel_launch(void* const* d_in, const int* in_sizes, int n_in,
                              void* d_out, int out_size) {
    const float* x = (const float*)d_in[0];       // [4,2048,4096] fp32
    const int* wp = (const int*)d_in[1];          // [8388608] int32 (one byte each)
    const float* scale = (const float*)d_in[2];   // [262144] fp32
    const float* bias = (const float*)d_in[3];    // [4096] fp32
    float* out = (float*)d_out;                   // [4,2048,4096] fp32

    dequant_kernel<<<(N_TOTAL * K_TOTAL / 2 + 255) / 256, 256>>>(wp, scale);
    xround_kernel<<<(size_t)M_TOTAL * K_TOTAL / 4 / 256, 256>>>(x);

    dim3 grid(N_TOTAL / BN, M_TOTAL / BM);  // (32, 64)
    gemm_kernel<<<grid, 256>>>(bias, out);
}

// round 10
// speedup vs baseline: 1.2156x; 1.2156x over previous
#include <cuda_runtime.h>
#include <cstdint>

// ---------------------------------------------------------------------------
// Problem constants
// ---------------------------------------------------------------------------
#define M_TOTAL 8192   // 4 * 2048
#define N_TOTAL 4096   // OUT_FEATURES
#define K_TOTAL 4096   // IN_FEATURES

#define K_BLKS (K_TOTAL / 32)   // 128
#define M_BLKS (M_TOTAL / 128)  // 64
#define N_BLKS (N_TOTAL / 128)  // 32

// GEMM tiling
#define BM 256
#define BN 128
#define BK 32
#define STAGES 3
#define NKT K_BLKS              // 128 k-steps of 32

// Fragment-packed scratch:
// g_X: [kt][m_blk128][m_tile(8)][k_tile(4)][lane(32)] x float4
//      float4 = {X[gr][gc], X[gr+8][gc], X[gr][gc+4], X[gr+8][gc+4]}  (A frag a0..a3)
// g_W: [kt][n_blk128][n_pair(8)][k_tile(4)][lane(32)] x float4
//      float4 = {W[np16+gr][gc], W[np16+gr][gc+4], W[np16+8+gr][gc], W[np16+8+gr][gc+4]}
__device__ __align__(1024) float g_W[(size_t)N_TOTAL * K_TOTAL];
__device__ __align__(1024) float g_X[(size_t)M_TOTAL * K_TOTAL];

__constant__ float c_codebook[16] = {
    0.0f, 0.0052f, 0.6667f, 1.0f, 0.3333f, 0.5f, 0.1667f, 0.25f,
    0.0f, -0.0052f, -0.6667f, -1.0f, -0.3333f, -0.5f, -0.1667f, -0.25f};

__device__ __forceinline__ float tf32_rna(float x) {
    uint32_t o;
    asm("cvt.rna.tf32.f32 %0, %1;" : "=r"(o) : "f"(x));
    return __uint_as_float(o);
}

__device__ __forceinline__ void cp_async16(void* smem_dst, const void* gsrc) {
    uint32_t d = (uint32_t)__cvta_generic_to_shared(smem_dst);
    asm volatile("cp.async.cg.shared.global [%0], [%1], 16;\n" ::"r"(d), "l"(gsrc));
}
__device__ __forceinline__ void cp_commit() {
    asm volatile("cp.async.commit_group;\n" ::: "memory");
}
template <int N>
__device__ __forceinline__ void cp_wait() {
    asm volatile("cp.async.wait_group %0;\n" ::"n"(N) : "memory");
}

// ---------------------------------------------------------------------------
// Kernel 1: dequant packed FP4 -> g_W in B-fragment-major layout.
// Grid (K_BLKS, N_BLKS), 256 threads. CTA covers 128 n-rows x 32 k.
// Stage through SMEM: coalesced packed read -> LUT*scale*tf32 -> fragment write.
// All 32 k of a row sit in one 64-wide scale block half => one scale per row.
// ---------------------------------------------------------------------------
__global__ __launch_bounds__(256) void dequant_pack(const int4* __restrict__ wp4,
                                                    const float* __restrict__ scale) {
    __shared__ float s[128 * 36];
    const int kb = blockIdx.x, nb = blockIdx.y;
    const int tid = threadIdx.x;

    // Load+dequant: 2 threads per row; each handles 8 ints = 16 values.
    {
        const int row = tid >> 1;
        const int half = tid & 1;
        const int ibase = (nb * 128 + row) * 2048 + kb * 16 + half * 8;  // int index
        const int4 p0 = wp4[ibase >> 2];
        const int4 p1 = wp4[(ibase >> 2) + 1];
        const float sc = scale[(nb * 128 + row) * 64 + (kb >> 1)];
        const int v[8] = {p0.x, p0.y, p0.z, p0.w, p1.x, p1.y, p1.z, p1.w};
        float* srow = &s[row * 36 + half * 16];
#pragma unroll
        for (int j = 0; j < 8; j++) {
            srow[2 * j] = tf32_rna(c_codebook[(v[j] >> 4) & 15] * sc);
            srow[2 * j + 1] = tf32_rna(c_codebook[v[j] & 15] * sc);
        }
    }
    __syncthreads();

    // Write out fragment-major (conflict-free smem reads: (4*gr+gc) spans 0..31).
    float4* gw4 = reinterpret_cast<float4*>(g_W);
#pragma unroll
    for (int j = 0; j < 4; j++) {
        const int idx = tid + j * 256;           // 0..1023
        const int np = idx >> 7;                 // n-pair 0..7
        const int kt = (idx >> 5) & 3;           // k-tile 0..3
        const int lane = idx & 31;
        const int gr = lane >> 2, gc = lane & 3;
        float4 v;
        v.x = s[(np * 16 + gr) * 36 + kt * 8 + gc];
        v.y = s[(np * 16 + gr) * 36 + kt * 8 + gc + 4];
        v.z = s[(np * 16 + 8 + gr) * 36 + kt * 8 + gc];
        v.w = s[(np * 16 + 8 + gr) * 36 + kt * 8 + gc + 4];
        gw4[(size_t)(kb * N_BLKS + nb) * 1024 + idx] = v;
    }
}

// ---------------------------------------------------------------------------
// Kernel 2: x -> tf32-rounded, A-fragment-major g_X.
// Grid (K_BLKS, M_BLKS), 256 threads. CTA covers 128 m-rows x 32 k.
// ---------------------------------------------------------------------------
__global__ __launch_bounds__(256) void xpack(const float4* __restrict__ x4) {
    __shared__ float s[128 * 36];
    const int kb = blockIdx.x, mb = blockIdx.y;
    const int tid = threadIdx.x;

#pragma unroll
    for (int j = 0; j < 4; j++) {
        const int idx = tid + j * 256;           // 0..1023 float4s
        const int row = idx >> 3;
        const int c4 = idx & 7;
        float4 v = x4[(size_t)(mb * 128 + row) * (K_TOTAL / 4) + kb * 8 + c4];
        v.x = tf32_rna(v.x); v.y = tf32_rna(v.y);
        v.z = tf32_rna(v.z); v.w = tf32_rna(v.w);
        *reinterpret_cast<float4*>(&s[row * 36 + c4 * 4]) = v;  // 16B-aligned (36%4==0)
    }
    __syncthreads();

    float4* gx4 = reinterpret_cast<float4*>(g_X);
#pragma unroll
    for (int j = 0; j < 4; j++) {
        const int idx = tid + j * 256;
        const int mt = idx >> 7;                 // m-tile 0..7
        const int kt = (idx >> 5) & 3;
        const int lane = idx & 31;
        const int gr = lane >> 2, gc = lane & 3;
        float4 v;  // a0,a1,a2,a3
        v.x = s[(mt * 16 + gr) * 36 + kt * 8 + gc];
        v.y = s[(mt * 16 + 8 + gr) * 36 + kt * 8 + gc];
        v.z = s[(mt * 16 + gr) * 36 + kt * 8 + gc + 4];
        v.w = s[(mt * 16 + 8 + gr) * 36 + kt * 8 + gc + 4];
        gx4[(size_t)(kb * M_BLKS + mb) * 1024 + idx] = v;
    }
}

// ---------------------------------------------------------------------------
// Kernel 3: GEMM  out = X @ W^T + bias.
// CTA 256x128, 512 threads (16 warps, 4m x 4n), warp tile 64x32.
// 3-stage cp.async ring; fragment loads are LDS.128, conflict-free.
// ---------------------------------------------------------------------------
__global__ __launch_bounds__(512, 1) void gemm_frag(const float* __restrict__ bias,
                                                    float* __restrict__ out) {
    extern __shared__ __align__(16) float4 smem4[];
    float4* As = smem4;              // STAGES * 2048
    float4* Bs = smem4 + STAGES * 2048;  // STAGES * 1024

    const int tid = threadIdx.x;
    const int wid = tid >> 5;
    const int lane = tid & 31;
    const int gr = lane >> 2, gc = lane & 3;
    const int warp_mt = (wid & 3) * 4;   // m-tile base (warp covers 4 of 16)
    const int warp_np = (wid >> 2) * 2;  // n-pair base (warp covers 2 of 8)
    const int mb = blockIdx.y;           // 256-row tile
    const int nb = blockIdx.x;           // 128-col tile

    const float4* gX = reinterpret_cast<const float4*>(g_X);
    const float4* gW = reinterpret_cast<const float4*>(g_W);

    auto load_stage = [&](int s, int kt) {
        const float4* a_src = &gX[(size_t)(kt * M_BLKS + mb * 2) * 1024];  // 2048 f4
        const float4* b_src = &gW[(size_t)(kt * N_BLKS + nb) * 1024];      // 1024 f4
#pragma unroll
        for (int j = 0; j < 4; j++)
            cp_async16(&As[s * 2048 + tid + j * 512], &a_src[tid + j * 512]);
#pragma unroll
        for (int j = 0; j < 2; j++)
            cp_async16(&Bs[s * 1024 + tid + j * 512], &b_src[tid + j * 512]);
        cp_commit();
    };

    float acc[4][4][4];
#pragma unroll
    for (int i = 0; i < 4; i++)
#pragma unroll
        for (int j = 0; j < 4; j++)
#pragma unroll
            for (int r = 0; r < 4; r++) acc[i][j][r] = 0.0f;

    load_stage(0, 0);
    load_stage(1, 1);

    int cur = 0;
    for (int kt = 0; kt < NKT; kt++) {
        cp_wait<1>();
        __syncthreads();
        if (kt + 2 < NKT) {
            int nxt = cur + 2; if (nxt >= STAGES) nxt -= STAGES;
            load_stage(nxt, kt + 2);
        } else {
            cp_commit();  // keep group count consistent for cp_wait<1>
        }

        const float4* a_s = &As[cur * 2048];
        const float4* b_s = &Bs[cur * 1024];
#pragma unroll
        for (int ks = 0; ks < 4; ks++) {
            float4 af[4], bf[2];
#pragma unroll
            for (int tm = 0; tm < 4; tm++)
                af[tm] = a_s[((warp_mt + tm) * 4 + ks) * 32 + lane];
#pragma unroll
            for (int p = 0; p < 2; p++)
                bf[p] = b_s[((warp_np + p) * 4 + ks) * 32 + lane];
#pragma unroll
            for (int tm = 0; tm < 4; tm++) {
                const uint32_t a0 = __float_as_uint(af[tm].x);
                const uint32_t a1 = __float_as_uint(af[tm].y);
                const uint32_t a2 = __float_as_uint(af[tm].z);
                const uint32_t a3 = __float_as_uint(af[tm].w);
#pragma unroll
                for (int tn = 0; tn < 4; tn++) {
                    const float4& bv = bf[tn >> 1];
                    const uint32_t b0 = __float_as_uint((tn & 1) ? bv.z : bv.x);
                    const uint32_t b1 = __float_as_uint((tn & 1) ? bv.w : bv.y);
                    asm volatile(
                        "mma.sync.aligned.m16n8k8.row.col.f32.tf32.tf32.f32 "
                        "{%0,%1,%2,%3}, {%4,%5,%6,%7}, {%8,%9}, {%0,%1,%2,%3};"
                        : "+f"(acc[tm][tn][0]), "+f"(acc[tm][tn][1]),
                          "+f"(acc[tm][tn][2]), "+f"(acc[tm][tn][3])
                        : "r"(a0), "r"(a1), "r"(a2), "r"(a3), "r"(b0), "r"(b1));
                }
            }
        }
        cur++; if (cur >= STAGES) cur -= STAGES;
    }

    // Epilogue: add bias, float2 stores.
    const int warp_m = warp_mt * 16;   // 0..192
    const int warp_n = warp_np * 16;   // 0..96
#pragma unroll
    for (int tm = 0; tm < 4; tm++) {
        const int m = mb * BM + warp_m + tm * 16 + gr;
#pragma unroll
        for (int tn = 0; tn < 4; tn++) {
            const int n = nb * BN + warp_n + (tn >> 1) * 16 + (tn & 1) * 8 + gc * 2;
            const float b0 = __ldg(&bias[n]);
            const float b1 = __ldg(&bias[n + 1]);
            float2 v0 = make_float2(acc[tm][tn][0] + b0, acc[tm][tn][1] + b1);
            float2 v1 = make_float2(acc[tm][tn][2] + b0, acc[tm][tn][3] + b1);
            *reinterpret_cast<float2*>(&out[(size_t)m * N_TOTAL + n]) = v0;
            *reinterpret_cast<float2*>(&out[(size_t)(m + 8) * N_TOTAL + n]) = v1;
        }
    }
}

// ---------------------------------------------------------------------------
extern "C" void kernel_launch(void* const* d_in, const int* in_sizes, int n_in,
                              void* d_out, int out_size) {
    const float* x = (const float*)d_in[0];       // [4,2048,4096] fp32
    const int* wp = (const int*)d_in[1];          // [8388608] int32 (one byte each)
    const float* scale = (const float*)d_in[2];   // [262144] fp32
    const float* bias = (const float*)d_in[3];    // [4096] fp32
    float* out = (float*)d_out;                   // [4,2048,4096] fp32

    dequant_pack<<<dim3(K_BLKS, N_BLKS), 256>>>((const int4*)wp, scale);
    xpack<<<dim3(K_BLKS, M_BLKS), 256>>>((const float4*)x);

    const int smem_bytes = STAGES * (2048 + 1024) * sizeof(float4);  // 147456
    static bool attr_set = false;
    if (!attr_set) {
        cudaFuncSetAttribute(gemm_frag, cudaFuncAttributeMaxDynamicSharedMemorySize,
                             smem_bytes);
        attr_set = true;
    }
    dim3 grid(N_TOTAL / BN, M_TOTAL / BM);  // (32, 32)
    gemm_frag<<<grid, 512, smem_bytes>>>(bias, out);
}

// round 14
// speedup vs baseline: 2.3543x; 1.9367x over previous
#include <cuda_runtime.h>
#include <cuda_fp16.h>
#include <cstdint>

// ---------------------------------------------------------------------------
// Problem constants
// ---------------------------------------------------------------------------
#define M_TOTAL 8192   // 4 * 2048
#define N_TOTAL 4096   // OUT_FEATURES
#define K_TOTAL 4096   // IN_FEATURES

#define K16_TOTAL (K_TOTAL / 16)   // 256 k16-steps
#define M_BLKS (M_TOTAL / 128)     // 64
#define N_BLKS (N_TOTAL / 128)     // 32

// GEMM tiling
#define BM 256
#define BN 128
#define BK 64
#define STAGES 3
#define NKT (K_TOTAL / BK)         // 64

// Fragment-packed fp16 scratch.
// g_X4: [k16][m_blk128][mtile(8)][lane(32)] -> uint4 = A frag {a0,a1,a2,a3}
//   a0={X[R+gr][kb+2gc],X[R+gr][kb+2gc+1]}, a1=rows+8, a2/a3 = cols+8
// g_W4: [k16][n_blk128][npair(8)][lane(32)] -> uint4 = {b0,b1 of n8=2p; b0,b1 of n8=2p+1}
//   b0={W[n8*8+gr][kb+2gc],W[n8*8+gr][kb+2gc+1]}, b1 = cols+8
__device__ __align__(1024) uint4 g_X4[(size_t)M_TOTAL * K_TOTAL / 8];  // 64 MB
__device__ __align__(1024) uint4 g_W4[(size_t)N_TOTAL * K_TOTAL / 8];  // 32 MB

__constant__ float c_codebook[16] = {
    0.0f, 0.0052f, 0.6667f, 1.0f, 0.3333f, 0.5f, 0.1667f, 0.25f,
    0.0f, -0.0052f, -0.6667f, -1.0f, -0.3333f, -0.5f, -0.1667f, -0.25f};

__device__ __forceinline__ uint32_t pack_h2(float a, float b) {
    __half2 h = __floats2half2_rn(a, b);
    return *reinterpret_cast<uint32_t*>(&h);
}

__device__ __forceinline__ void cp_async16(void* smem_dst, const void* gsrc) {
    uint32_t d = (uint32_t)__cvta_generic_to_shared(smem_dst);
    asm volatile("cp.async.cg.shared.global [%0], [%1], 16;\n" ::"r"(d), "l"(gsrc));
}
__device__ __forceinline__ void cp_commit() {
    asm volatile("cp.async.commit_group;\n" ::: "memory");
}
template <int N>
__device__ __forceinline__ void cp_wait() {
    asm volatile("cp.async.wait_group %0;\n" ::"n"(N) : "memory");
}

// ---------------------------------------------------------------------------
// Kernel 1: dequant packed FP4 -> g_W4 (fp16, B-fragment-major).
// Grid (K_TOTAL/32, N_BLKS), 256 threads. CTA = 128 n-rows x 32 k (2 k16 steps).
// All 32 k of a row sit inside one 64-wide scale block => one scale per row.
// ---------------------------------------------------------------------------
__global__ __launch_bounds__(256) void dequant_pack(const int4* __restrict__ wp4,
                                                    const float* __restrict__ scale) {
    __shared__ __align__(16) __half s[128][40];
    const int kb = blockIdx.x, nb = blockIdx.y;   // kb: 32-k chunk
    const int tid = threadIdx.x;

    // Phase 1: load + dequant. 2 threads/row, 8 packed ints (16 weights) each.
    {
        const int row = tid >> 1;
        const int half = tid & 1;
        const int ibase = (nb * 128 + row) * 2048 + kb * 16 + half * 8;  // int index
        const int4 p0 = wp4[ibase >> 2];
        const int4 p1 = wp4[(ibase >> 2) + 1];
        const float sc = scale[(nb * 128 + row) * 64 + (kb >> 1)];
        const int v[8] = {p0.x, p0.y, p0.z, p0.w, p1.x, p1.y, p1.z, p1.w};
        uint32_t* srow = reinterpret_cast<uint32_t*>(&s[row][half * 16]);
#pragma unroll
        for (int j = 0; j < 8; j++)
            srow[j] = pack_h2(c_codebook[(v[j] >> 4) & 15] * sc,
                              c_codebook[v[j] & 15] * sc);
    }
    __syncthreads();

    // Phase 2: emit B fragments. 512 uint4 per CTA (2 k16 x 8 npair x 32 lanes).
#pragma unroll
    for (int j = 0; j < 2; j++) {
        const int idx = tid + j * 256;
        const int k16l = idx >> 8;
        const int np = (idx >> 5) & 7;
        const int lane = idx & 31;
        const int gr = lane >> 2, gc = lane & 3;
        const int c0 = k16l * 16 + 2 * gc;
        uint4 v;
        {   // n8 = 2*np
            const int r = (np * 2) * 8 + gr;
            v.x = *reinterpret_cast<const uint32_t*>(&s[r][c0]);
            v.y = *reinterpret_cast<const uint32_t*>(&s[r][c0 + 8]);
        }
        {   // n8 = 2*np+1
            const int r = (np * 2 + 1) * 8 + gr;
            v.z = *reinterpret_cast<const uint32_t*>(&s[r][c0]);
            v.w = *reinterpret_cast<const uint32_t*>(&s[r][c0 + 8]);
        }
        const int k16g = kb * 2 + k16l;
        g_W4[((size_t)k16g * N_BLKS + nb) * 256 + np * 32 + lane] = v;
    }
}

// ---------------------------------------------------------------------------
// Kernel 2: x -> fp16 A-fragment-major g_X4.
// Grid (K_TOTAL/32, M_BLKS), 256 threads. CTA = 128 m-rows x 32 k.
// ---------------------------------------------------------------------------
__global__ __launch_bounds__(256) void xpack(const float4* __restrict__ x4) {
    __shared__ __align__(16) __half s[128][40];
    const int kb = blockIdx.x, mb = blockIdx.y;
    const int tid = threadIdx.x;

    // Phase 1: coalesced read + convert. 1024 float4 per CTA.
#pragma unroll
    for (int j = 0; j < 4; j++) {
        const int idx = tid + j * 256;
        const int row = idx >> 3;
        const int c4 = idx & 7;
        float4 v = x4[(size_t)(mb * 128 + row) * (K_TOTAL / 4) + kb * 8 + c4];
        uint2 h;
        h.x = pack_h2(v.x, v.y);
        h.y = pack_h2(v.z, v.w);
        *reinterpret_cast<uint2*>(&s[row][c4 * 4]) = h;
    }
    __syncthreads();

    // Phase 2: emit A fragments. 512 uint4 per CTA (2 k16 x 8 mtile x 32 lanes).
#pragma unroll
    for (int j = 0; j < 2; j++) {
        const int idx = tid + j * 256;
        const int k16l = idx >> 8;
        const int mt = (idx >> 5) & 7;
        const int lane = idx & 31;
        const int gr = lane >> 2, gc = lane & 3;
        const int c0 = k16l * 16 + 2 * gc;
        const int r0 = mt * 16 + gr;
        uint4 v;
        v.x = *reinterpret_cast<const uint32_t*>(&s[r0][c0]);        // a0
        v.y = *reinterpret_cast<const uint32_t*>(&s[r0 + 8][c0]);    // a1
        v.z = *reinterpret_cast<const uint32_t*>(&s[r0][c0 + 8]);    // a2
        v.w = *reinterpret_cast<const uint32_t*>(&s[r0 + 8][c0 + 8]); // a3
        const int k16g = kb * 2 + k16l;
        g_X4[((size_t)k16g * M_BLKS + mb) * 256 + mt * 32 + lane] = v;
    }
}

// ---------------------------------------------------------------------------
// Kernel 3: GEMM  out = X @ W^T + bias   (fp16 inputs, fp32 accumulate)
// CTA 256x128, 512 threads (16 warps: 4m x 4n), warp tile 64x32.
// 3-stage cp.async ring (48 KB/stage); m16n8k16 HMMA; LDS.128 fragment loads.
// ---------------------------------------------------------------------------
__global__ __launch_bounds__(512, 1) void gemm_h(const float* __restrict__ bias,
                                                 float* __restrict__ out) {
    extern __shared__ __align__(16) uint4 smem4[];
    uint4* As = smem4;                   // STAGES * 2048 uint4
    uint4* Bs = smem4 + STAGES * 2048;   // STAGES * 1024 uint4

    const int tid = threadIdx.x;
    const int wid = tid >> 5;
    const int lane = tid & 31;
    const int gr = lane >> 2, gc = lane & 3;
    const int warp_mt0 = (wid & 3) * 4;  // mtile base (of 16 mtiles x 16 rows)
    const int warp_np = (wid >> 2) * 2;  // npair base (of 8 npairs x 16 cols)
    const int mb = blockIdx.y;           // 256-row tile
    const int nb = blockIdx.x;           // 128-col tile

    auto load_stage = [&](int st, int kt) {
        // A: 8 chunks of 256 uint4 -> (k16 local 0..3) x (mblk half 0..1)
#pragma unroll
        for (int j = 0; j < 4; j++) {
            const int idx = tid + j * 512;
            const int chunk = idx >> 8;
            const int within = idx & 255;
            const int k16 = kt * 4 + (chunk >> 1);
            const int mblk = mb * 2 + (chunk & 1);
            cp_async16(&As[st * 2048 + idx],
                       &g_X4[((size_t)k16 * M_BLKS + mblk) * 256 + within]);
        }
        // B: 4 chunks of 256 uint4 -> k16 local 0..3
#pragma unroll
        for (int j = 0; j < 2; j++) {
            const int idx = tid + j * 512;
            const int k16 = kt * 4 + (idx >> 8);
            cp_async16(&Bs[st * 1024 + idx],
                       &g_W4[((size_t)k16 * N_BLKS + nb) * 256 + (idx & 255)]);
        }
        cp_commit();
    };

    float acc[4][4][4];
#pragma unroll
    for (int i = 0; i < 4; i++)
#pragma unroll
        for (int j = 0; j < 4; j++)
#pragma unroll
            for (int r = 0; r < 4; r++) acc[i][j][r] = 0.0f;

    load_stage(0, 0);
    load_stage(1, 1);

    int cur = 0;
    for (int kt = 0; kt < NKT; kt++) {
        cp_wait<1>();
        __syncthreads();
        if (kt + 2 < NKT) {
            int nxt = cur + 2; if (nxt >= STAGES) nxt -= STAGES;
            load_stage(nxt, kt + 2);
        } else {
            cp_commit();  // keep group count consistent for cp_wait<1>
        }

        const uint4* a_s = &As[cur * 2048];
        const uint4* b_s = &Bs[cur * 1024];
#pragma unroll
        for (int ks = 0; ks < 4; ks++) {
            uint4 af[4], bf[2];
#pragma unroll
            for (int tm = 0; tm < 4; tm++) {
                const int mt = warp_mt0 + tm;
                af[tm] = a_s[(ks * 2 + (mt >> 3)) * 256 + (mt & 7) * 32 + lane];
            }
#pragma unroll
            for (int p = 0; p < 2; p++)
                bf[p] = b_s[ks * 256 + (warp_np + p) * 32 + lane];
#pragma unroll
            for (int tm = 0; tm < 4; tm++) {
#pragma unroll
                for (int tn = 0; tn < 4; tn++) {
                    const uint4& bv = bf[tn >> 1];
                    const uint32_t b0 = (tn & 1) ? bv.z : bv.x;
                    const uint32_t b1 = (tn & 1) ? bv.w : bv.y;
                    asm volatile(
                        "mma.sync.aligned.m16n8k16.row.col.f32.f16.f16.f32 "
                        "{%0,%1,%2,%3}, {%4,%5,%6,%7}, {%8,%9}, {%0,%1,%2,%3};"
                        : "+f"(acc[tm][tn][0]), "+f"(acc[tm][tn][1]),
                          "+f"(acc[tm][tn][2]), "+f"(acc[tm][tn][3])
                        : "r"(af[tm].x), "r"(af[tm].y), "r"(af[tm].z), "r"(af[tm].w),
                          "r"(b0), "r"(b1));
                }
            }
        }
        cur++; if (cur >= STAGES) cur -= STAGES;
    }

    // Epilogue: add bias, float2 stores.
#pragma unroll
    for (int tm = 0; tm < 4; tm++) {
        const int m = mb * BM + (warp_mt0 + tm) * 16 + gr;
#pragma unroll
        for (int tn = 0; tn < 4; tn++) {
            const int p = tn >> 1, q = tn & 1;
            const int n = nb * BN + (warp_np + p) * 16 + q * 8 + gc * 2;
            const float b0 = __ldg(&bias[n]);
            const float b1 = __ldg(&bias[n + 1]);
            float2 v0 = make_float2(acc[tm][tn][0] + b0, acc[tm][tn][1] + b1);
            float2 v1 = make_float2(acc[tm][tn][2] + b0, acc[tm][tn][3] + b1);
            *reinterpret_cast<float2*>(&out[(size_t)m * N_TOTAL + n]) = v0;
            *reinterpret_cast<float2*>(&out[(size_t)(m + 8) * N_TOTAL + n]) = v1;
        }
    }
}

// ---------------------------------------------------------------------------
extern "C" void kernel_launch(void* const* d_in, const int* in_sizes, int n_in,
                              void* d_out, int out_size) {
    const float* x = (const float*)d_in[0];       // [4,2048,4096] fp32
    const int* wp = (const int*)d_in[1];          // [8388608] int32 (one byte each)
    const float* scale = (const float*)d_in[2];   // [262144] fp32
    const float* bias = (const float*)d_in[3];    // [4096] fp32
    float* out = (float*)d_out;                   // [4,2048,4096] fp32

    dequant_pack<<<dim3(K_TOTAL / 32, N_BLKS), 256>>>((const int4*)wp, scale);
    xpack<<<dim3(K_TOTAL / 32, M_BLKS), 256>>>((const float4*)x);

    const int smem_bytes = STAGES * (2048 + 1024) * sizeof(uint4);  // 147456
    static bool attr_set = false;
    if (!attr_set) {
        cudaFuncSetAttribute(gemm_h, cudaFuncAttributeMaxDynamicSharedMemorySize,
                             smem_bytes);
        attr_set = true;
    }
    dim3 grid(N_TOTAL / BN, M_TOTAL / BM);  // (32, 32)
    gemm_h<<<grid, 512, smem_bytes>>>(bias, out);
}